// round 1
// baseline (speedup 1.0000x reference)
#include <cuda_runtime.h>
#include <cstdint>

#define B_  8
#define S_  2048
#define D_  512
#define NH_ 8
#define HD_ 64
#define M_  (B_*S_)

#define QT_ 128   // queries per attention block
#define KT_ 64    // keys per tile
#define PAD 68    // smem row stride (floats), keeps float4 alignment, avoids bank conflicts

// Scratch (allocation-free rule: __device__ globals)
__device__ float g_Q[(size_t)M_ * D_];
__device__ float g_K[(size_t)M_ * D_];
__device__ float g_V[(size_t)M_ * D_];
__device__ float g_A[(size_t)M_ * D_];

// ---------------------------------------------------------------------------
// Tiled fp32 GEMM: Y[M,N] = A[M,K] @ W[K,N] (+ bias[N] if bias != nullptr)
// BM=128, BN=128, BK=16, 256 threads, 8x8 per thread.
// ---------------------------------------------------------------------------
__global__ __launch_bounds__(256) void gemm128x128(
    const float* __restrict__ A, const float* __restrict__ W,
    const float* __restrict__ bias, float* __restrict__ Y,
    int M, int N, int K)
{
    __shared__ __align__(16) float As[16][128];   // transposed: As[k][m]
    __shared__ __align__(16) float Bs[16][128];   // Bs[k][n]

    const int tid = threadIdx.x;
    const int tx  = tid & 15;
    const int ty  = tid >> 4;
    const int m0  = blockIdx.y * 128;
    const int n0  = blockIdx.x * 128;

    float acc[8][8];
#pragma unroll
    for (int i = 0; i < 8; ++i)
#pragma unroll
        for (int j = 0; j < 8; ++j) acc[i][j] = 0.f;

    const int ar = tid >> 2;          // 0..63
    const int ac = (tid & 3) << 2;    // 0,4,8,12
    const int bk = tid >> 5;          // 0..7
    const int bn = (tid & 31) << 2;   // 0..124

    for (int k0 = 0; k0 < K; k0 += 16) {
#pragma unroll
        for (int it = 0; it < 2; ++it) {
            int row = ar + it * 64;
            float4 v = *(const float4*)(A + (size_t)(m0 + row) * K + k0 + ac);
            As[ac + 0][row] = v.x;
            As[ac + 1][row] = v.y;
            As[ac + 2][row] = v.z;
            As[ac + 3][row] = v.w;
        }
#pragma unroll
        for (int it = 0; it < 2; ++it) {
            int kk = bk + it * 8;
            *(float4*)&Bs[kk][bn] =
                *(const float4*)(W + (size_t)(k0 + kk) * N + n0 + bn);
        }
        __syncthreads();

#pragma unroll
        for (int k = 0; k < 16; ++k) {
            float a[8], b[8];
            *(float4*)&a[0] = *(const float4*)&As[k][ty * 8];
            *(float4*)&a[4] = *(const float4*)&As[k][ty * 8 + 4];
            *(float4*)&b[0] = *(const float4*)&Bs[k][tx * 8];
            *(float4*)&b[4] = *(const float4*)&Bs[k][tx * 8 + 4];
#pragma unroll
            for (int i = 0; i < 8; ++i)
#pragma unroll
                for (int j = 0; j < 8; ++j) acc[i][j] += a[i] * b[j];
        }
        __syncthreads();
    }

    float bb[8];
#pragma unroll
    for (int j = 0; j < 8; ++j) bb[j] = bias ? bias[n0 + tx * 8 + j] : 0.f;

#pragma unroll
    for (int i = 0; i < 8; ++i) {
        int row = m0 + ty * 8 + i;
        float4 r0, r1;
        r0.x = acc[i][0] + bb[0]; r0.y = acc[i][1] + bb[1];
        r0.z = acc[i][2] + bb[2]; r0.w = acc[i][3] + bb[3];
        r1.x = acc[i][4] + bb[4]; r1.y = acc[i][5] + bb[5];
        r1.z = acc[i][6] + bb[6]; r1.w = acc[i][7] + bb[7];
        *(float4*)(Y + (size_t)row * N + n0 + tx * 8)     = r0;
        *(float4*)(Y + (size_t)row * N + n0 + tx * 8 + 4) = r1;
    }
}

// ---------------------------------------------------------------------------
// Flash attention, fp32. One block per (b, h, 128-query tile).
// Q tile resident in smem; loop over 32 key tiles of 64; online softmax.
// Thread grid 16x16: thread (tx,ty) owns rows ty*8..+7, cols tx*4..+3.
// ---------------------------------------------------------------------------
__global__ __launch_bounds__(256, 2) void attn_kernel(
    const float* __restrict__ Q, const float* __restrict__ K,
    const float* __restrict__ V, float* __restrict__ O)
{
    extern __shared__ float sm[];
    float* Qs = sm;                         // [128][PAD]  (row, d)
    float* Kt = Qs + QT_ * PAD;             // [64][PAD]   transposed: (d, key)
    float* Vs = Kt + HD_ * PAD;             // [64][PAD]   (key, d)
    float* Ps = Vs + KT_ * PAD;             // [128][PAD]  (row, key)

    const int tid = threadIdx.x;
    const int tx  = tid & 15;
    const int ty  = tid >> 4;
    const int bh  = blockIdx.x;
    const int b   = bh / NH_;
    const int h   = bh % NH_;
    const int q0  = blockIdx.y * QT_;

    const float NEG_INF = __int_as_float(0xff800000u);

    // ---- load Q tile [128 x 64] into smem ----
    const size_t baseQ = ((size_t)b * S_ + q0) * D_ + h * HD_;
#pragma unroll
    for (int it = 0; it < 8; ++it) {
        int idx = tid + it * 256;
        int row = idx >> 4;
        int d4  = (idx & 15) << 2;
        float4 v = *(const float4*)(Q + baseQ + (size_t)row * D_ + d4);
        *(float4*)&Qs[row * PAD + d4] = v;
    }

    float mrow[8], lrow[8], o[8][4];
#pragma unroll
    for (int i = 0; i < 8; ++i) {
        mrow[i] = NEG_INF; lrow[i] = 0.f;
#pragma unroll
        for (int j = 0; j < 4; ++j) o[i][j] = 0.f;
    }

    for (int kt = 0; kt < S_ / KT_; ++kt) {
        __syncthreads();   // prior PV reads done before smem tiles are overwritten

        // ---- load K (transposed) and V tiles ----
        const size_t baseK = ((size_t)b * S_ + kt * KT_) * D_ + h * HD_;
#pragma unroll
        for (int it = 0; it < 4; ++it) {
            int idx = tid + it * 256;
            int key = idx >> 4;
            int d4  = (idx & 15) << 2;
            float4 kv = *(const float4*)(K + baseK + (size_t)key * D_ + d4);
            Kt[(d4 + 0) * PAD + key] = kv.x;
            Kt[(d4 + 1) * PAD + key] = kv.y;
            Kt[(d4 + 2) * PAD + key] = kv.z;
            Kt[(d4 + 3) * PAD + key] = kv.w;
            float4 vv = *(const float4*)(V + baseK + (size_t)key * D_ + d4);
            *(float4*)&Vs[key * PAD + d4] = vv;
        }
        __syncthreads();

        // ---- S = Q K^T (8x4 per thread) ----
        float s[8][4];
#pragma unroll
        for (int i = 0; i < 8; ++i)
#pragma unroll
            for (int j = 0; j < 4; ++j) s[i][j] = 0.f;

#pragma unroll
        for (int k = 0; k < HD_; k += 4) {
            float4 b0 = *(const float4*)&Kt[(k + 0) * PAD + tx * 4];
            float4 b1 = *(const float4*)&Kt[(k + 1) * PAD + tx * 4];
            float4 b2 = *(const float4*)&Kt[(k + 2) * PAD + tx * 4];
            float4 b3 = *(const float4*)&Kt[(k + 3) * PAD + tx * 4];
#pragma unroll
            for (int i = 0; i < 8; ++i) {
                float4 a = *(const float4*)&Qs[(ty * 8 + i) * PAD + k];
                s[i][0] += a.x * b0.x + a.y * b1.x + a.z * b2.x + a.w * b3.x;
                s[i][1] += a.x * b0.y + a.y * b1.y + a.z * b2.y + a.w * b3.y;
                s[i][2] += a.x * b0.z + a.y * b1.z + a.z * b2.z + a.w * b3.z;
                s[i][3] += a.x * b0.w + a.y * b1.w + a.z * b2.w + a.w * b3.w;
            }
        }

        // ---- online softmax (row reductions over the 16 lanes of each row) ----
#pragma unroll
        for (int i = 0; i < 8; ++i) {
            float s0 = s[i][0] * 0.125f;   // 1/sqrt(64)
            float s1 = s[i][1] * 0.125f;
            float s2 = s[i][2] * 0.125f;
            float s3 = s[i][3] * 0.125f;
            float rmax = fmaxf(fmaxf(s0, s1), fmaxf(s2, s3));
#pragma unroll
            for (int msk = 1; msk < 16; msk <<= 1)
                rmax = fmaxf(rmax, __shfl_xor_sync(0xffffffffu, rmax, msk));
            float mnew = fmaxf(mrow[i], rmax);
            float corr = __expf(mrow[i] - mnew);
            float p0 = __expf(s0 - mnew);
            float p1 = __expf(s1 - mnew);
            float p2 = __expf(s2 - mnew);
            float p3 = __expf(s3 - mnew);
            float rsum = p0 + p1 + p2 + p3;
#pragma unroll
            for (int msk = 1; msk < 16; msk <<= 1)
                rsum += __shfl_xor_sync(0xffffffffu, rsum, msk);
            lrow[i] = lrow[i] * corr + rsum;
            mrow[i] = mnew;
            o[i][0] *= corr; o[i][1] *= corr; o[i][2] *= corr; o[i][3] *= corr;
            *(float4*)&Ps[(ty * 8 + i) * PAD + tx * 4] = make_float4(p0, p1, p2, p3);
        }
        __syncthreads();

        // ---- O += P V ----
#pragma unroll
        for (int kk = 0; kk < KT_; kk += 4) {
            float4 b0 = *(const float4*)&Vs[(kk + 0) * PAD + tx * 4];
            float4 b1 = *(const float4*)&Vs[(kk + 1) * PAD + tx * 4];
            float4 b2 = *(const float4*)&Vs[(kk + 2) * PAD + tx * 4];
            float4 b3 = *(const float4*)&Vs[(kk + 3) * PAD + tx * 4];
#pragma unroll
            for (int i = 0; i < 8; ++i) {
                float4 p = *(const float4*)&Ps[(ty * 8 + i) * PAD + kk];
                o[i][0] += p.x * b0.x + p.y * b1.x + p.z * b2.x + p.w * b3.x;
                o[i][1] += p.x * b0.y + p.y * b1.y + p.z * b2.y + p.w * b3.y;
                o[i][2] += p.x * b0.z + p.y * b1.z + p.z * b2.z + p.w * b3.z;
                o[i][3] += p.x * b0.w + p.y * b1.w + p.z * b2.w + p.w * b3.w;
            }
        }
    }

    // ---- epilogue: normalize and store ----
#pragma unroll
    for (int i = 0; i < 8; ++i) {
        float inv = 1.f / lrow[i];
        int row = q0 + ty * 8 + i;
        float4 r = make_float4(o[i][0] * inv, o[i][1] * inv,
                               o[i][2] * inv, o[i][3] * inv);
        *(float4*)(O + ((size_t)b * S_ + row) * D_ + h * HD_ + tx * 4) = r;
    }
}

// ---------------------------------------------------------------------------
// Launch: 3 projections -> attention -> output projection (+bias)
// Input order: key, query, value, Wq, Wk, Wv, Wo, bo
// ---------------------------------------------------------------------------
extern "C" void kernel_launch(void* const* d_in, const int* in_sizes, int n_in,
                              void* d_out, int out_size)
{
    const float* key   = (const float*)d_in[0];
    const float* query = (const float*)d_in[1];
    const float* value = (const float*)d_in[2];
    const float* Wq    = (const float*)d_in[3];
    const float* Wk    = (const float*)d_in[4];
    const float* Wv    = (const float*)d_in[5];
    const float* Wo    = (const float*)d_in[6];
    const float* bo    = (const float*)d_in[7];
    float* out = (float*)d_out;

    float *Qp, *Kp, *Vp, *Ap;
    cudaGetSymbolAddress((void**)&Qp, g_Q);
    cudaGetSymbolAddress((void**)&Kp, g_K);
    cudaGetSymbolAddress((void**)&Vp, g_V);
    cudaGetSymbolAddress((void**)&Ap, g_A);

    const int smem_bytes = (QT_ * PAD + HD_ * PAD + KT_ * PAD + QT_ * PAD) * 4;
    cudaFuncSetAttribute(attn_kernel,
                         cudaFuncAttributeMaxDynamicSharedMemorySize, smem_bytes);

    dim3 gg(D_ / 128, M_ / 128);
    gemm128x128<<<gg, 256>>>(query, Wq, nullptr, Qp, M_, D_, D_);
    gemm128x128<<<gg, 256>>>(key,   Wk, nullptr, Kp, M_, D_, D_);
    gemm128x128<<<gg, 256>>>(value, Wv, nullptr, Vp, M_, D_, D_);

    attn_kernel<<<dim3(B_ * NH_, S_ / QT_), 256, smem_bytes>>>(Qp, Kp, Vp, Ap);

    gemm128x128<<<gg, 256>>>(Ap, Wo, bo, out, M_, D_, D_);
}

// round 3
// speedup vs baseline: 2.4526x; 2.4526x over previous
#include <cuda_runtime.h>
#include <cuda_bf16.h>
#include <cstdint>

#define B_  8
#define S_  2048
#define D_  512
#define NH_ 8
#define HD_ 64
#define M_  (B_*S_)

// ---------------- scratch (__device__ globals) ------------------------------
__device__ __nv_bfloat16 g_ahi[(size_t)M_ * D_];
__device__ __nv_bfloat16 g_alo[(size_t)M_ * D_];
__device__ __nv_bfloat16 g_whi[(size_t)D_ * D_];
__device__ __nv_bfloat16 g_wlo[(size_t)D_ * D_];
__device__ __nv_bfloat16 g_qhi[(size_t)M_ * D_];
__device__ __nv_bfloat16 g_qlo[(size_t)M_ * D_];
__device__ __nv_bfloat16 g_khi[(size_t)M_ * D_];
__device__ __nv_bfloat16 g_klo[(size_t)M_ * D_];
__device__ __nv_bfloat16 g_vhi[(size_t)M_ * D_];
__device__ __nv_bfloat16 g_vlo[(size_t)M_ * D_];

// ---------------- helpers ----------------------------------------------------
__device__ __forceinline__ uint32_t smem_u32(const void* p) {
    uint32_t a;
    asm("{ .reg .u64 t; cvta.to.shared.u64 t, %1; cvt.u32.u64 %0, t; }" : "=r"(a) : "l"(p));
    return a;
}
__device__ __forceinline__ void ldm4(uint32_t* r, uint32_t a) {
    asm volatile("ldmatrix.sync.aligned.m8n8.x4.shared.b16 {%0,%1,%2,%3}, [%4];"
        : "=r"(r[0]), "=r"(r[1]), "=r"(r[2]), "=r"(r[3]) : "r"(a));
}
__device__ __forceinline__ void ldm4t(uint32_t* r, uint32_t a) {
    asm volatile("ldmatrix.sync.aligned.m8n8.x4.trans.shared.b16 {%0,%1,%2,%3}, [%4];"
        : "=r"(r[0]), "=r"(r[1]), "=r"(r[2]), "=r"(r[3]) : "r"(a));
}
__device__ __forceinline__ void mma16816(float* d, const uint32_t* a, const uint32_t* b) {
    asm volatile("mma.sync.aligned.m16n8k16.row.col.f32.bf16.bf16.f32 "
        "{%0,%1,%2,%3}, {%4,%5,%6,%7}, {%8,%9}, {%0,%1,%2,%3};"
        : "+f"(d[0]), "+f"(d[1]), "+f"(d[2]), "+f"(d[3])
        : "r"(a[0]), "r"(a[1]), "r"(a[2]), "r"(a[3]), "r"(b[0]), "r"(b[1]));
}
__device__ __forceinline__ uint32_t pack_bf(float a, float b) {
    __nv_bfloat162 t = __floats2bfloat162_rn(a, b);
    return *reinterpret_cast<uint32_t*>(&t);
}
__device__ __forceinline__ void split_pair(float a, float b, uint32_t& hi, uint32_t& lo) {
    __nv_bfloat16 ha = __float2bfloat16(a), hb = __float2bfloat16(b);
    __nv_bfloat162 hv(ha, hb);
    hi = *reinterpret_cast<uint32_t*>(&hv);
    lo = pack_bf(a - __bfloat162float(ha), b - __bfloat162float(hb));
}

// ---------------- prep: fp32 -> bf16 hi/lo -----------------------------------
__global__ __launch_bounds__(256) void split_act(
    const float* __restrict__ x, __nv_bfloat16* __restrict__ hi,
    __nv_bfloat16* __restrict__ lo, int n)
{
    int i = (blockIdx.x * 256 + threadIdx.x) * 4;
    if (i >= n) return;
    float4 v = *(const float4*)(x + i);
    uint32_t h0, l0, h1, l1;
    split_pair(v.x, v.y, h0, l0);
    split_pair(v.z, v.w, h1, l1);
    *(uint32_t*)(hi + i)     = h0;
    *(uint32_t*)(hi + i + 2) = h1;
    *(uint32_t*)(lo + i)     = l0;
    *(uint32_t*)(lo + i + 2) = l1;
}

// fp32 W [K,N] -> bf16 hi/lo transposed to [N,K]
__global__ __launch_bounds__(256) void split_wt(
    const float* __restrict__ W, __nv_bfloat16* __restrict__ hi,
    __nv_bfloat16* __restrict__ lo)
{
    int t = blockIdx.x * 256 + threadIdx.x;
    if (t >= D_ * D_) return;
    int k = t & (D_ - 1);
    int n = t >> 9;
    float v = W[(size_t)k * D_ + n];
    __nv_bfloat16 h = __float2bfloat16(v);
    hi[t] = h;
    lo[t] = __float2bfloat16(v - __bfloat162float(h));
}

// ---------------- GEMM: Y[M,512] = (Ahi+Alo) @ (Whi+Wlo)^T (W stored [N,K]) --
// 128x128 tile, 256 threads (8 warps, 2x4 warp grid, 64x32 per warp), BK=32.
#define GS 40     // smem stride (bf16 elems) => 80B rows, ldmatrix conflict-free

__global__ __launch_bounds__(256) void gemm_mma(
    const __nv_bfloat16* __restrict__ Ahi, const __nv_bfloat16* __restrict__ Alo,
    const __nv_bfloat16* __restrict__ Whi, const __nv_bfloat16* __restrict__ Wlo,
    const float* __restrict__ bias, float* __restrict__ Yf,
    __nv_bfloat16* __restrict__ Yhi, __nv_bfloat16* __restrict__ Ylo,
    float scale, int mode)
{
    __shared__ __align__(16) __nv_bfloat16 sA[2][128 * GS];
    __shared__ __align__(16) __nv_bfloat16 sB[2][128 * GS];

    const int tid  = threadIdx.x;
    const int lane = tid & 31;
    const int wid  = tid >> 5;
    const int wm   = wid >> 2;          // 0..1
    const int wn   = wid & 3;           // 0..3
    const int m0   = blockIdx.y * 128;
    const int n0   = blockIdx.x * 128;
    const int g    = lane >> 2;
    const int tc   = lane & 3;

    float acc[4][4][4];
#pragma unroll
    for (int i = 0; i < 4; ++i)
#pragma unroll
        for (int j = 0; j < 4; ++j)
#pragma unroll
            for (int e = 0; e < 4; ++e) acc[i][j][e] = 0.f;

    const uint32_t sAh = smem_u32(sA[0]), sAl = smem_u32(sA[1]);
    const uint32_t sBh = smem_u32(sB[0]), sBl = smem_u32(sB[1]);

    for (int c = 0; c < 16; ++c) {
        __syncthreads();
#pragma unroll
        for (int i = 0; i < 2; ++i) {
            int idx = tid + i * 256;
            int row = idx >> 2, q = (idx & 3) << 3;
            size_t ga = (size_t)(m0 + row) * D_ + c * 32 + q;
            size_t gb = (size_t)(n0 + row) * D_ + c * 32 + q;
            *(uint4*)&sA[0][row * GS + q] = *(const uint4*)(Ahi + ga);
            *(uint4*)&sA[1][row * GS + q] = *(const uint4*)(Alo + ga);
            *(uint4*)&sB[0][row * GS + q] = *(const uint4*)(Whi + gb);
            *(uint4*)&sB[1][row * GS + q] = *(const uint4*)(Wlo + gb);
        }
        __syncthreads();

#pragma unroll
        for (int s = 0; s < 2; ++s) {
            uint32_t ah[4][4], al[4][4], bh[4][2], bl[4][2];
            const uint32_t aofs =
                ((wm * 64 + (lane & 15)) * GS + s * 16 + (lane >> 4) * 8) * 2;
#pragma unroll
            for (int mf = 0; mf < 4; ++mf) {
                ldm4(ah[mf], sAh + aofs + mf * 16 * GS * 2);
                ldm4(al[mf], sAl + aofs + mf * 16 * GS * 2);
            }
            const int bn = wn * 32 + (lane & 7) + (lane >> 4) * 8;
            const int bk = s * 16 + ((lane >> 3) & 1) * 8;
#pragma unroll
            for (int jp = 0; jp < 2; ++jp) {
                uint32_t r[4];
                ldm4(r, sBh + ((bn + jp * 16) * GS + bk) * 2);
                bh[jp * 2][0] = r[0]; bh[jp * 2][1] = r[1];
                bh[jp * 2 + 1][0] = r[2]; bh[jp * 2 + 1][1] = r[3];
                ldm4(r, sBl + ((bn + jp * 16) * GS + bk) * 2);
                bl[jp * 2][0] = r[0]; bl[jp * 2][1] = r[1];
                bl[jp * 2 + 1][0] = r[2]; bl[jp * 2 + 1][1] = r[3];
            }
#pragma unroll
            for (int mf = 0; mf < 4; ++mf)
#pragma unroll
                for (int nf = 0; nf < 4; ++nf) {
                    mma16816(acc[mf][nf], ah[mf], bh[nf]);
                    mma16816(acc[mf][nf], ah[mf], bl[nf]);
                    mma16816(acc[mf][nf], al[mf], bh[nf]);
                }
        }
    }

    // epilogue
#pragma unroll
    for (int mf = 0; mf < 4; ++mf)
#pragma unroll
        for (int nf = 0; nf < 4; ++nf) {
            int row = m0 + wm * 64 + mf * 16 + g;
            int col = n0 + wn * 32 + nf * 8 + tc * 2;
            float d0 = acc[mf][nf][0], d1 = acc[mf][nf][1];
            float d2 = acc[mf][nf][2], d3 = acc[mf][nf][3];
            if (mode == 0) {
                float b0 = bias[col], b1 = bias[col + 1];
                *(float2*)(Yf + (size_t)row * D_ + col)       = make_float2(d0 + b0, d1 + b1);
                *(float2*)(Yf + (size_t)(row + 8) * D_ + col) = make_float2(d2 + b0, d3 + b1);
            } else {
                uint32_t h0, l0, h1, l1;
                split_pair(d0 * scale, d1 * scale, h0, l0);
                split_pair(d2 * scale, d3 * scale, h1, l1);
                *(uint32_t*)(Yhi + (size_t)row * D_ + col)       = h0;
                *(uint32_t*)(Ylo + (size_t)row * D_ + col)       = l0;
                *(uint32_t*)(Yhi + (size_t)(row + 8) * D_ + col) = h1;
                *(uint32_t*)(Ylo + (size_t)(row + 8) * D_ + col) = l1;
            }
        }
}

// ---------------- attention (FA2-style, mma.sync split-bf16) -----------------
// 128 threads, 4 warps; 64-query tile per block; warp owns 16 rows.
#define AS 72     // smem stride (bf16 elems) => 144B rows

__global__ __launch_bounds__(128) void attn_mma(
    const __nv_bfloat16* __restrict__ Qh, const __nv_bfloat16* __restrict__ Ql,
    const __nv_bfloat16* __restrict__ Kh, const __nv_bfloat16* __restrict__ Kl,
    const __nv_bfloat16* __restrict__ Vh, const __nv_bfloat16* __restrict__ Vl,
    __nv_bfloat16* __restrict__ Ohi, __nv_bfloat16* __restrict__ Olo)
{
    extern __shared__ __align__(16) __nv_bfloat16 smb[];
    // elem offsets: Qh 0, Ql 1, Kh 2, Kl 3, Vh 4, Vl 5  (each 64*AS)
    const int tid  = threadIdx.x;
    const int lane = tid & 31;
    const int wid  = tid >> 5;
    const int bh   = blockIdx.x;
    const int b    = bh >> 3;
    const int h    = bh & 7;
    const int q0   = blockIdx.y * 64;
    const int g    = lane >> 2;
    const int tc   = lane & 3;

    const uint32_t sb  = smem_u32(smb);
    const uint32_t oQh = 0,            oQl = 64 * AS * 2;
    const uint32_t oKh = 2 * 64 * AS * 2, oKl = 3 * 64 * AS * 2;
    const uint32_t oVh = 4 * 64 * AS * 2, oVl = 5 * 64 * AS * 2;

    // ---- load Q tile (64 x 64 bf16, hi+lo) ----
#pragma unroll
    for (int i = 0; i < 4; ++i) {
        int idx = tid + i * 128;
        int row = idx >> 3, q = (idx & 7) << 3;
        size_t gofs = ((size_t)(b * S_ + q0 + row)) * D_ + h * HD_ + q;
        *(uint4*)&smb[row * AS + q]           = *(const uint4*)(Qh + gofs);
        *(uint4*)&smb[64 * AS + row * AS + q] = *(const uint4*)(Ql + gofs);
    }
    __syncthreads();

    // ---- hoist Q fragments ----
    uint32_t qh[4][4], ql[4][4];
    {
        const uint32_t qofs = ((wid * 16 + (lane & 15)) * AS + (lane >> 4) * 8) * 2;
#pragma unroll
        for (int s = 0; s < 4; ++s) {
            ldm4(qh[s], sb + oQh + qofs + s * 32);
            ldm4(ql[s], sb + oQl + qofs + s * 32);
        }
    }

    const float NEG_INF = __int_as_float(0xff800000u);
    float fo[8][4];
#pragma unroll
    for (int j = 0; j < 8; ++j)
#pragma unroll
        for (int e = 0; e < 4; ++e) fo[j][e] = 0.f;
    float m0r = NEG_INF, m1r = NEG_INF, l0 = 0.f, l1 = 0.f;

    for (int kt = 0; kt < S_ / 64; ++kt) {
        __syncthreads();
        // ---- load K/V tiles hi+lo ----
#pragma unroll
        for (int i = 0; i < 4; ++i) {
            int idx = tid + i * 128;
            int row = idx >> 3, q = (idx & 7) << 3;
            size_t gofs = ((size_t)(b * S_ + kt * 64 + row)) * D_ + h * HD_ + q;
            *(uint4*)&smb[2 * 64 * AS + row * AS + q] = *(const uint4*)(Kh + gofs);
            *(uint4*)&smb[3 * 64 * AS + row * AS + q] = *(const uint4*)(Kl + gofs);
            *(uint4*)&smb[4 * 64 * AS + row * AS + q] = *(const uint4*)(Vh + gofs);
            *(uint4*)&smb[5 * 64 * AS + row * AS + q] = *(const uint4*)(Vl + gofs);
        }
        __syncthreads();

        // ---- S = Q K^T ----
        float fs[8][4];
#pragma unroll
        for (int j = 0; j < 8; ++j)
#pragma unroll
            for (int e = 0; e < 4; ++e) fs[j][e] = 0.f;

#pragma unroll
        for (int s = 0; s < 4; ++s) {
            uint32_t bkh[8][2], bkl[8][2];
            const int bn = (lane & 7) + (lane >> 4) * 8;
            const int bk = s * 16 + ((lane >> 3) & 1) * 8;
#pragma unroll
            for (int jp = 0; jp < 4; ++jp) {
                uint32_t r[4];
                ldm4(r, sb + oKh + ((bn + jp * 16) * AS + bk) * 2);
                bkh[jp * 2][0] = r[0]; bkh[jp * 2][1] = r[1];
                bkh[jp * 2 + 1][0] = r[2]; bkh[jp * 2 + 1][1] = r[3];
                ldm4(r, sb + oKl + ((bn + jp * 16) * AS + bk) * 2);
                bkl[jp * 2][0] = r[0]; bkl[jp * 2][1] = r[1];
                bkl[jp * 2 + 1][0] = r[2]; bkl[jp * 2 + 1][1] = r[3];
            }
#pragma unroll
            for (int j = 0; j < 8; ++j) {
                mma16816(fs[j], qh[s], bkh[j]);
                mma16816(fs[j], qh[s], bkl[j]);
                mma16816(fs[j], ql[s], bkh[j]);
            }
        }

        // ---- online softmax ----
        float mx0 = NEG_INF, mx1 = NEG_INF;
#pragma unroll
        for (int j = 0; j < 8; ++j) {
            mx0 = fmaxf(mx0, fmaxf(fs[j][0], fs[j][1]));
            mx1 = fmaxf(mx1, fmaxf(fs[j][2], fs[j][3]));
        }
        mx0 = fmaxf(mx0, __shfl_xor_sync(0xffffffffu, mx0, 1));
        mx0 = fmaxf(mx0, __shfl_xor_sync(0xffffffffu, mx0, 2));
        mx1 = fmaxf(mx1, __shfl_xor_sync(0xffffffffu, mx1, 1));
        mx1 = fmaxf(mx1, __shfl_xor_sync(0xffffffffu, mx1, 2));
        float mn0 = fmaxf(m0r, mx0), mn1 = fmaxf(m1r, mx1);
        float c0 = __expf(m0r - mn0), c1 = __expf(m1r - mn1);
        m0r = mn0; m1r = mn1;

        float s0 = 0.f, s1 = 0.f;
#pragma unroll
        for (int j = 0; j < 8; ++j) {
            fs[j][0] = __expf(fs[j][0] - mn0);
            fs[j][1] = __expf(fs[j][1] - mn0);
            fs[j][2] = __expf(fs[j][2] - mn1);
            fs[j][3] = __expf(fs[j][3] - mn1);
            s0 += fs[j][0] + fs[j][1];
            s1 += fs[j][2] + fs[j][3];
        }
        s0 += __shfl_xor_sync(0xffffffffu, s0, 1);
        s0 += __shfl_xor_sync(0xffffffffu, s0, 2);
        s1 += __shfl_xor_sync(0xffffffffu, s1, 1);
        s1 += __shfl_xor_sync(0xffffffffu, s1, 2);
        l0 = l0 * c0 + s0;
        l1 = l1 * c1 + s1;
#pragma unroll
        for (int j = 0; j < 8; ++j) {
            fo[j][0] *= c0; fo[j][1] *= c0;
            fo[j][2] *= c1; fo[j][3] *= c1;
        }

        // ---- P (split hi/lo) as A fragments: D->A register identity ----
        uint32_t ph[4][4], pl[4][4];
#pragma unroll
        for (int kk = 0; kk < 4; ++kk) {
            split_pair(fs[2 * kk][0],     fs[2 * kk][1],     ph[kk][0], pl[kk][0]);
            split_pair(fs[2 * kk][2],     fs[2 * kk][3],     ph[kk][1], pl[kk][1]);
            split_pair(fs[2 * kk + 1][0], fs[2 * kk + 1][1], ph[kk][2], pl[kk][2]);
            split_pair(fs[2 * kk + 1][2], fs[2 * kk + 1][3], ph[kk][3], pl[kk][3]);
        }

        // ---- O += P V ----
#pragma unroll
        for (int kk = 0; kk < 4; ++kk) {
            uint32_t bvh[8][2], bvl[8][2];
            const int vk = kk * 16 + (lane & 7) + ((lane >> 3) & 1) * 8;
            const int vd = (lane >> 4) * 8;
#pragma unroll
            for (int jp = 0; jp < 4; ++jp) {
                uint32_t r[4];
                ldm4t(r, sb + oVh + (vk * AS + vd + jp * 16) * 2);
                bvh[jp * 2][0] = r[0]; bvh[jp * 2][1] = r[1];
                bvh[jp * 2 + 1][0] = r[2]; bvh[jp * 2 + 1][1] = r[3];
                ldm4t(r, sb + oVl + (vk * AS + vd + jp * 16) * 2);
                bvl[jp * 2][0] = r[0]; bvl[jp * 2][1] = r[1];
                bvl[jp * 2 + 1][0] = r[2]; bvl[jp * 2 + 1][1] = r[3];
            }
#pragma unroll
            for (int j = 0; j < 8; ++j) {
                mma16816(fo[j], ph[kk], bvh[j]);
                mma16816(fo[j], ph[kk], bvl[j]);
                mma16816(fo[j], pl[kk], bvh[j]);
            }
        }
    }

    // ---- epilogue: normalize, split to bf16 hi/lo for final projection ----
    float i0 = 1.f / l0, i1 = 1.f / l1;
    const size_t r0 = (size_t)(b * S_ + q0 + wid * 16 + g) * D_ + h * HD_;
    const size_t r1 = r0 + 8 * D_;
#pragma unroll
    for (int j = 0; j < 8; ++j) {
        int col = j * 8 + tc * 2;
        uint32_t h0, l0u, h1, l1u;
        split_pair(fo[j][0] * i0, fo[j][1] * i0, h0, l0u);
        split_pair(fo[j][2] * i1, fo[j][3] * i1, h1, l1u);
        *(uint32_t*)(Ohi + r0 + col) = h0;
        *(uint32_t*)(Olo + r0 + col) = l0u;
        *(uint32_t*)(Ohi + r1 + col) = h1;
        *(uint32_t*)(Olo + r1 + col) = l1u;
    }
}

// ---------------- launch ------------------------------------------------------
extern "C" void kernel_launch(void* const* d_in, const int* in_sizes, int n_in,
                              void* d_out, int out_size)
{
    const float* key   = (const float*)d_in[0];
    const float* query = (const float*)d_in[1];
    const float* value = (const float*)d_in[2];
    const float* Wq    = (const float*)d_in[3];
    const float* Wk    = (const float*)d_in[4];
    const float* Wv    = (const float*)d_in[5];
    const float* Wo    = (const float*)d_in[6];
    const float* bo    = (const float*)d_in[7];
    float* out = (float*)d_out;

    __nv_bfloat16 *ahi, *alo, *whi, *wlo, *qhi, *qlo, *khi, *klo, *vhi, *vlo;
    cudaGetSymbolAddress((void**)&ahi, g_ahi);
    cudaGetSymbolAddress((void**)&alo, g_alo);
    cudaGetSymbolAddress((void**)&whi, g_whi);
    cudaGetSymbolAddress((void**)&wlo, g_wlo);
    cudaGetSymbolAddress((void**)&qhi, g_qhi);
    cudaGetSymbolAddress((void**)&qlo, g_qlo);
    cudaGetSymbolAddress((void**)&khi, g_khi);
    cudaGetSymbolAddress((void**)&klo, g_klo);
    cudaGetSymbolAddress((void**)&vhi, g_vhi);
    cudaGetSymbolAddress((void**)&vlo, g_vlo);

    const int attn_smem = 6 * 64 * AS * 2;   // 55296 B
    cudaFuncSetAttribute(attn_mma,
                         cudaFuncAttributeMaxDynamicSharedMemorySize, attn_smem);

    const int nact = M_ * D_;
    const int act_blocks = nact / 4 / 256;
    const int wt_blocks = (D_ * D_ + 255) / 256;
    dim3 gg(D_ / 128, M_ / 128);

    // Q projection (pre-scaled by 1/sqrt(HD))
    split_wt<<<wt_blocks, 256>>>(Wq, whi, wlo);
    split_act<<<act_blocks, 256>>>(query, ahi, alo, nact);
    gemm_mma<<<gg, 256>>>(ahi, alo, whi, wlo, nullptr, nullptr, qhi, qlo, 0.125f, 1);
    // K projection
    split_wt<<<wt_blocks, 256>>>(Wk, whi, wlo);
    split_act<<<act_blocks, 256>>>(key, ahi, alo, nact);
    gemm_mma<<<gg, 256>>>(ahi, alo, whi, wlo, nullptr, nullptr, khi, klo, 1.0f, 1);
    // V projection
    split_wt<<<wt_blocks, 256>>>(Wv, whi, wlo);
    split_act<<<act_blocks, 256>>>(value, ahi, alo, nact);
    gemm_mma<<<gg, 256>>>(ahi, alo, whi, wlo, nullptr, nullptr, vhi, vlo, 1.0f, 1);

    // attention -> writes bf16 hi/lo directly into ahi/alo
    attn_mma<<<dim3(B_ * NH_, S_ / 64), 128, attn_smem>>>(
        qhi, qlo, khi, klo, vhi, vlo, ahi, alo);

    // output projection (+bias, fp32 out)
    split_wt<<<wt_blocks, 256>>>(Wo, whi, wlo);
    gemm_mma<<<gg, 256>>>(ahi, alo, whi, wlo, bo, out, nullptr, nullptr, 1.0f, 0);
}

// round 4
// speedup vs baseline: 2.7316x; 1.1137x over previous
#include <cuda_runtime.h>
#include <cuda_bf16.h>
#include <cstdint>

#define B_  8
#define S_  2048
#define D_  512
#define NH_ 8
#define HD_ 64
#define M_  (B_*S_)

// ---------------- scratch (__device__ globals) ------------------------------
__device__ __nv_bfloat16 g_ahi[(size_t)M_ * D_];
__device__ __nv_bfloat16 g_alo[(size_t)M_ * D_];
__device__ __nv_bfloat16 g_whi[(size_t)D_ * D_];
__device__ __nv_bfloat16 g_wlo[(size_t)D_ * D_];
__device__ __nv_bfloat16 g_qhi[(size_t)M_ * D_];
__device__ __nv_bfloat16 g_qlo[(size_t)M_ * D_];
__device__ __nv_bfloat16 g_khi[(size_t)M_ * D_];
__device__ __nv_bfloat16 g_klo[(size_t)M_ * D_];
__device__ __nv_bfloat16 g_vhi[(size_t)M_ * D_];
__device__ __nv_bfloat16 g_vlo[(size_t)M_ * D_];

// ---------------- helpers ----------------------------------------------------
__device__ __forceinline__ uint32_t smem_u32(const void* p) {
    uint32_t a;
    asm("{ .reg .u64 t; cvta.to.shared.u64 t, %1; cvt.u32.u64 %0, t; }" : "=r"(a) : "l"(p));
    return a;
}
__device__ __forceinline__ void ldm4(uint32_t* r, uint32_t a) {
    asm volatile("ldmatrix.sync.aligned.m8n8.x4.shared.b16 {%0,%1,%2,%3}, [%4];"
        : "=r"(r[0]), "=r"(r[1]), "=r"(r[2]), "=r"(r[3]) : "r"(a));
}
__device__ __forceinline__ void ldm4t(uint32_t* r, uint32_t a) {
    asm volatile("ldmatrix.sync.aligned.m8n8.x4.trans.shared.b16 {%0,%1,%2,%3}, [%4];"
        : "=r"(r[0]), "=r"(r[1]), "=r"(r[2]), "=r"(r[3]) : "r"(a));
}
__device__ __forceinline__ void mma16816(float* d, const uint32_t* a, const uint32_t* b) {
    asm volatile("mma.sync.aligned.m16n8k16.row.col.f32.bf16.bf16.f32 "
        "{%0,%1,%2,%3}, {%4,%5,%6,%7}, {%8,%9}, {%0,%1,%2,%3};"
        : "+f"(d[0]), "+f"(d[1]), "+f"(d[2]), "+f"(d[3])
        : "r"(a[0]), "r"(a[1]), "r"(a[2]), "r"(a[3]), "r"(b[0]), "r"(b[1]));
}
__device__ __forceinline__ uint32_t pack_bf(float a, float b) {
    __nv_bfloat162 t = __floats2bfloat162_rn(a, b);
    return *reinterpret_cast<uint32_t*>(&t);
}
__device__ __forceinline__ void split_pair(float a, float b, uint32_t& hi, uint32_t& lo) {
    __nv_bfloat16 ha = __float2bfloat16(a), hb = __float2bfloat16(b);
    __nv_bfloat162 hv(ha, hb);
    hi = *reinterpret_cast<uint32_t*>(&hv);
    lo = pack_bf(a - __bfloat162float(ha), b - __bfloat162float(hb));
}
#define CPA16(dst, src) asm volatile("cp.async.cg.shared.global [%0], [%1], 16;" :: "r"(dst), "l"(src))
#define CP_COMMIT()     asm volatile("cp.async.commit_group;" ::: "memory")
#define CP_WAIT1()      asm volatile("cp.async.wait_group 1;" ::: "memory")
#define CP_WAIT0()      asm volatile("cp.async.wait_group 0;" ::: "memory")

// ---------------- prep: fp32 -> bf16 hi/lo -----------------------------------
__global__ __launch_bounds__(256) void split_act(
    const float* __restrict__ x, __nv_bfloat16* __restrict__ hi,
    __nv_bfloat16* __restrict__ lo, int n)
{
    int i = (blockIdx.x * 256 + threadIdx.x) * 4;
    if (i >= n) return;
    float4 v = *(const float4*)(x + i);
    uint32_t h0, l0, h1, l1;
    split_pair(v.x, v.y, h0, l0);
    split_pair(v.z, v.w, h1, l1);
    *(uint32_t*)(hi + i)     = h0;
    *(uint32_t*)(hi + i + 2) = h1;
    *(uint32_t*)(lo + i)     = l0;
    *(uint32_t*)(lo + i + 2) = l1;
}

__global__ __launch_bounds__(256) void split_wt(
    const float* __restrict__ W, __nv_bfloat16* __restrict__ hi,
    __nv_bfloat16* __restrict__ lo)
{
    int t = blockIdx.x * 256 + threadIdx.x;
    if (t >= D_ * D_) return;
    int k = t & (D_ - 1);
    int n = t >> 9;
    float v = W[(size_t)k * D_ + n];
    __nv_bfloat16 h = __float2bfloat16(v);
    hi[t] = h;
    lo[t] = __float2bfloat16(v - __bfloat162float(h));
}

// ---------------- GEMM (double-buffered cp.async) ----------------------------
// Y[M,512] = (Ahi+Alo) @ (Whi+Wlo)^T, W stored [N,K]. 128x128 tile, BK=32.
#define GS 40
#define GEMM_ARR (128 * GS * 2)        // bytes per array (10240)
#define GEMM_STAGE (4 * GEMM_ARR)      // 40960
#define GEMM_SMEM (2 * GEMM_STAGE)     // 81920

__global__ __launch_bounds__(256) void gemm_mma(
    const __nv_bfloat16* __restrict__ Ahi, const __nv_bfloat16* __restrict__ Alo,
    const __nv_bfloat16* __restrict__ Whi, const __nv_bfloat16* __restrict__ Wlo,
    const float* __restrict__ bias, float* __restrict__ Yf,
    __nv_bfloat16* __restrict__ Yhi, __nv_bfloat16* __restrict__ Ylo,
    float scale, int mode)
{
    extern __shared__ __align__(16) char smg[];
    const uint32_t sb = smem_u32(smg);

    const int tid  = threadIdx.x;
    const int lane = tid & 31;
    const int wid  = tid >> 5;
    const int wm   = wid >> 2;
    const int wn   = wid & 3;
    const int m0   = blockIdx.y * 128;
    const int n0   = blockIdx.x * 128;
    const int g    = lane >> 2;
    const int tc   = lane & 3;

    float acc[4][4][4];
#pragma unroll
    for (int i = 0; i < 4; ++i)
#pragma unroll
        for (int j = 0; j < 4; ++j)
#pragma unroll
            for (int e = 0; e < 4; ++e) acc[i][j][e] = 0.f;

    // prefetch helper: 2 chunks per array per thread
    const int prow = tid >> 2;
    const int pqb  = (tid & 3) << 4;                 // byte col 0/16/32/48
    auto prefetch = [&](int c, int st) {
        const uint32_t base = sb + st * GEMM_STAGE;
#pragma unroll
        for (int i = 0; i < 2; ++i) {
            int row = prow + i * 64;
            uint32_t so = row * (GS * 2) + pqb;
            size_t ga = (size_t)(m0 + row) * D_ + c * 32 + (pqb >> 1);
            size_t gb = (size_t)(n0 + row) * D_ + c * 32 + (pqb >> 1);
            CPA16(base + so,                ((const char*)(Ahi + ga)));
            CPA16(base + GEMM_ARR + so,     ((const char*)(Alo + ga)));
            CPA16(base + 2 * GEMM_ARR + so, ((const char*)(Whi + gb)));
            CPA16(base + 3 * GEMM_ARR + so, ((const char*)(Wlo + gb)));
        }
    };

    prefetch(0, 0);
    CP_COMMIT();

    const uint32_t aofs = ((wm * 64 + (lane & 15)) * GS + (lane >> 4) * 8) * 2;
    const int bn = wn * 32 + (lane & 7) + (lane >> 4) * 8;
    const int bko = ((lane >> 3) & 1) * 8;

    for (int c = 0; c < 16; ++c) {
        const int st = c & 1;
        if (c + 1 < 16) { prefetch(c + 1, st ^ 1); CP_COMMIT(); CP_WAIT1(); }
        else CP_WAIT0();
        __syncthreads();

        const uint32_t sAh = sb + st * GEMM_STAGE;
        const uint32_t sAl = sAh + GEMM_ARR;
        const uint32_t sBh = sAh + 2 * GEMM_ARR;
        const uint32_t sBl = sAh + 3 * GEMM_ARR;

#pragma unroll
        for (int s = 0; s < 2; ++s) {
            uint32_t ah[4][4], al[4][4], bh[4][2], bl[4][2];
#pragma unroll
            for (int mf = 0; mf < 4; ++mf) {
                ldm4(ah[mf], sAh + aofs + s * 32 + mf * 16 * GS * 2);
                ldm4(al[mf], sAl + aofs + s * 32 + mf * 16 * GS * 2);
            }
            const int bk = s * 16 + bko;
#pragma unroll
            for (int jp = 0; jp < 2; ++jp) {
                uint32_t r[4];
                ldm4(r, sBh + ((bn + jp * 16) * GS + bk) * 2);
                bh[jp * 2][0] = r[0]; bh[jp * 2][1] = r[1];
                bh[jp * 2 + 1][0] = r[2]; bh[jp * 2 + 1][1] = r[3];
                ldm4(r, sBl + ((bn + jp * 16) * GS + bk) * 2);
                bl[jp * 2][0] = r[0]; bl[jp * 2][1] = r[1];
                bl[jp * 2 + 1][0] = r[2]; bl[jp * 2 + 1][1] = r[3];
            }
#pragma unroll
            for (int mf = 0; mf < 4; ++mf)
#pragma unroll
                for (int nf = 0; nf < 4; ++nf) {
                    mma16816(acc[mf][nf], ah[mf], bh[nf]);
                    mma16816(acc[mf][nf], ah[mf], bl[nf]);
                    mma16816(acc[mf][nf], al[mf], bh[nf]);
                }
        }
        __syncthreads();
    }

#pragma unroll
    for (int mf = 0; mf < 4; ++mf)
#pragma unroll
        for (int nf = 0; nf < 4; ++nf) {
            int row = m0 + wm * 64 + mf * 16 + g;
            int col = n0 + wn * 32 + nf * 8 + tc * 2;
            float d0 = acc[mf][nf][0], d1 = acc[mf][nf][1];
            float d2 = acc[mf][nf][2], d3 = acc[mf][nf][3];
            if (mode == 0) {
                float b0 = bias[col], b1 = bias[col + 1];
                *(float2*)(Yf + (size_t)row * D_ + col)       = make_float2(d0 + b0, d1 + b1);
                *(float2*)(Yf + (size_t)(row + 8) * D_ + col) = make_float2(d2 + b0, d3 + b1);
            } else {
                uint32_t h0, l0, h1, l1;
                split_pair(d0 * scale, d1 * scale, h0, l0);
                split_pair(d2 * scale, d3 * scale, h1, l1);
                *(uint32_t*)(Yhi + (size_t)row * D_ + col)       = h0;
                *(uint32_t*)(Ylo + (size_t)row * D_ + col)       = l0;
                *(uint32_t*)(Yhi + (size_t)(row + 8) * D_ + col) = h1;
                *(uint32_t*)(Ylo + (size_t)(row + 8) * D_ + col) = l1;
            }
        }
}

// ---------------- attention (128-q tile, 8 warps, double-buffered K/V) -------
#define AS 72
#define KV_ARR (64 * AS * 2)           // 9216 B
#define KV_STAGE (4 * KV_ARR)          // 36864 B
#define Q_BYTES (2 * 128 * AS * 2)     // 36864 B
#define ATTN_SMEM (Q_BYTES + 2 * KV_STAGE)   // 110592 B

__global__ __launch_bounds__(256) void attn_mma(
    const __nv_bfloat16* __restrict__ Qh, const __nv_bfloat16* __restrict__ Ql,
    const __nv_bfloat16* __restrict__ Kh, const __nv_bfloat16* __restrict__ Kl,
    const __nv_bfloat16* __restrict__ Vh, const __nv_bfloat16* __restrict__ Vl,
    __nv_bfloat16* __restrict__ Ohi, __nv_bfloat16* __restrict__ Olo)
{
    extern __shared__ __align__(16) char sma[];
    __nv_bfloat16* smb = (__nv_bfloat16*)sma;
    const uint32_t sb = smem_u32(sma);

    const int tid  = threadIdx.x;
    const int lane = tid & 31;
    const int wid  = tid >> 5;
    const int bh   = blockIdx.x;
    const int b    = bh >> 3;
    const int h    = bh & 7;
    const int q0   = blockIdx.y * 128;
    const int g    = lane >> 2;
    const int tc   = lane & 3;

    // ---- Q tile (128 x 64, hi+lo) ----
#pragma unroll
    for (int i = 0; i < 4; ++i) {
        int idx = tid + i * 256;
        int row = idx >> 3, q = (idx & 7) << 3;
        size_t gofs = ((size_t)(b * S_ + q0 + row)) * D_ + h * HD_ + q;
        *(uint4*)&smb[row * AS + q]            = *(const uint4*)(Qh + gofs);
        *(uint4*)&smb[128 * AS + row * AS + q] = *(const uint4*)(Ql + gofs);
    }

    // KV prefetch: 2 chunks per array per thread
    const int prow = tid >> 3;
    const int pqb  = (tid & 7) << 4;
    auto prefetch = [&](int kt, int st) {
        const uint32_t base = sb + Q_BYTES + st * KV_STAGE;
        size_t grow = (size_t)(b * S_ + kt * 64) * D_ + h * HD_;
#pragma unroll
        for (int i = 0; i < 2; ++i) {
            int row = prow + i * 32;
            uint32_t so = row * (AS * 2) + pqb;
            size_t go = grow + (size_t)row * D_ + (pqb >> 1);
            CPA16(base + so,              ((const char*)(Kh + go)));
            CPA16(base + KV_ARR + so,     ((const char*)(Kl + go)));
            CPA16(base + 2 * KV_ARR + so, ((const char*)(Vh + go)));
            CPA16(base + 3 * KV_ARR + so, ((const char*)(Vl + go)));
        }
    };
    prefetch(0, 0);
    CP_COMMIT();
    __syncthreads();

    // ---- hoist Q fragments ----
    uint32_t qh[4][4], ql[4][4];
    {
        const uint32_t qofs = ((wid * 16 + (lane & 15)) * AS + (lane >> 4) * 8) * 2;
#pragma unroll
        for (int s = 0; s < 4; ++s) {
            ldm4(qh[s], sb + qofs + s * 32);
            ldm4(ql[s], sb + (uint32_t)(128 * AS * 2) + qofs + s * 32);
        }
    }

    const float NEG_INF = __int_as_float(0xff800000u);
    float fo[8][4];
#pragma unroll
    for (int j = 0; j < 8; ++j)
#pragma unroll
        for (int e = 0; e < 4; ++e) fo[j][e] = 0.f;
    float m0r = NEG_INF, m1r = NEG_INF, l0 = 0.f, l1 = 0.f;

    const int bn  = (lane & 7) + (lane >> 4) * 8;
    const int bko = ((lane >> 3) & 1) * 8;
    const int vk0 = (lane & 7) + ((lane >> 3) & 1) * 8;
    const int vd  = (lane >> 4) * 8;

    for (int kt = 0; kt < S_ / 64; ++kt) {
        const int st = kt & 1;
        if (kt + 1 < S_ / 64) { prefetch(kt + 1, st ^ 1); CP_COMMIT(); CP_WAIT1(); }
        else CP_WAIT0();
        __syncthreads();

        const uint32_t oKh = sb + Q_BYTES + st * KV_STAGE;
        const uint32_t oKl = oKh + KV_ARR;
        const uint32_t oVh = oKh + 2 * KV_ARR;
        const uint32_t oVl = oKh + 3 * KV_ARR;

        // ---- S = Q K^T ----
        float fs[8][4];
#pragma unroll
        for (int j = 0; j < 8; ++j)
#pragma unroll
            for (int e = 0; e < 4; ++e) fs[j][e] = 0.f;

#pragma unroll
        for (int s = 0; s < 4; ++s) {
            uint32_t bkh[8][2], bkl[8][2];
            const int bk = s * 16 + bko;
#pragma unroll
            for (int jp = 0; jp < 4; ++jp) {
                uint32_t r[4];
                ldm4(r, oKh + ((bn + jp * 16) * AS + bk) * 2);
                bkh[jp * 2][0] = r[0]; bkh[jp * 2][1] = r[1];
                bkh[jp * 2 + 1][0] = r[2]; bkh[jp * 2 + 1][1] = r[3];
                ldm4(r, oKl + ((bn + jp * 16) * AS + bk) * 2);
                bkl[jp * 2][0] = r[0]; bkl[jp * 2][1] = r[1];
                bkl[jp * 2 + 1][0] = r[2]; bkl[jp * 2 + 1][1] = r[3];
            }
#pragma unroll
            for (int j = 0; j < 8; ++j) {
                mma16816(fs[j], qh[s], bkh[j]);
                mma16816(fs[j], qh[s], bkl[j]);
                mma16816(fs[j], ql[s], bkh[j]);
            }
        }

        // ---- online softmax ----
        float mx0 = NEG_INF, mx1 = NEG_INF;
#pragma unroll
        for (int j = 0; j < 8; ++j) {
            mx0 = fmaxf(mx0, fmaxf(fs[j][0], fs[j][1]));
            mx1 = fmaxf(mx1, fmaxf(fs[j][2], fs[j][3]));
        }
        mx0 = fmaxf(mx0, __shfl_xor_sync(0xffffffffu, mx0, 1));
        mx0 = fmaxf(mx0, __shfl_xor_sync(0xffffffffu, mx0, 2));
        mx1 = fmaxf(mx1, __shfl_xor_sync(0xffffffffu, mx1, 1));
        mx1 = fmaxf(mx1, __shfl_xor_sync(0xffffffffu, mx1, 2));
        float mn0 = fmaxf(m0r, mx0), mn1 = fmaxf(m1r, mx1);
        float c0 = __expf(m0r - mn0), c1 = __expf(m1r - mn1);
        m0r = mn0; m1r = mn1;

        float s0 = 0.f, s1 = 0.f;
#pragma unroll
        for (int j = 0; j < 8; ++j) {
            fs[j][0] = __expf(fs[j][0] - mn0);
            fs[j][1] = __expf(fs[j][1] - mn0);
            fs[j][2] = __expf(fs[j][2] - mn1);
            fs[j][3] = __expf(fs[j][3] - mn1);
            s0 += fs[j][0] + fs[j][1];
            s1 += fs[j][2] + fs[j][3];
        }
        s0 += __shfl_xor_sync(0xffffffffu, s0, 1);
        s0 += __shfl_xor_sync(0xffffffffu, s0, 2);
        s1 += __shfl_xor_sync(0xffffffffu, s1, 1);
        s1 += __shfl_xor_sync(0xffffffffu, s1, 2);
        l0 = l0 * c0 + s0;
        l1 = l1 * c1 + s1;
#pragma unroll
        for (int j = 0; j < 8; ++j) {
            fo[j][0] *= c0; fo[j][1] *= c0;
            fo[j][2] *= c1; fo[j][3] *= c1;
        }

        // ---- P (hi/lo) as A fragments ----
        uint32_t ph[4][4], pl[4][4];
#pragma unroll
        for (int kk = 0; kk < 4; ++kk) {
            split_pair(fs[2 * kk][0],     fs[2 * kk][1],     ph[kk][0], pl[kk][0]);
            split_pair(fs[2 * kk][2],     fs[2 * kk][3],     ph[kk][1], pl[kk][1]);
            split_pair(fs[2 * kk + 1][0], fs[2 * kk + 1][1], ph[kk][2], pl[kk][2]);
            split_pair(fs[2 * kk + 1][2], fs[2 * kk + 1][3], ph[kk][3], pl[kk][3]);
        }

        // ---- O += P V ----
#pragma unroll
        for (int kk = 0; kk < 4; ++kk) {
            uint32_t bvh[8][2], bvl[8][2];
            const int vk = kk * 16 + vk0;
#pragma unroll
            for (int jp = 0; jp < 4; ++jp) {
                uint32_t r[4];
                ldm4t(r, oVh + (vk * AS + vd + jp * 16) * 2);
                bvh[jp * 2][0] = r[0]; bvh[jp * 2][1] = r[1];
                bvh[jp * 2 + 1][0] = r[2]; bvh[jp * 2 + 1][1] = r[3];
                ldm4t(r, oVl + (vk * AS + vd + jp * 16) * 2);
                bvl[jp * 2][0] = r[0]; bvl[jp * 2][1] = r[1];
                bvl[jp * 2 + 1][0] = r[2]; bvl[jp * 2 + 1][1] = r[3];
            }
#pragma unroll
            for (int j = 0; j < 8; ++j) {
                mma16816(fo[j], ph[kk], bvh[j]);
                mma16816(fo[j], ph[kk], bvl[j]);
                mma16816(fo[j], pl[kk], bvh[j]);
            }
        }
        __syncthreads();
    }

    // ---- epilogue ----
    float i0 = 1.f / l0, i1 = 1.f / l1;
    const size_t r0 = (size_t)(b * S_ + q0 + wid * 16 + g) * D_ + h * HD_;
    const size_t r1 = r0 + 8 * D_;
#pragma unroll
    for (int j = 0; j < 8; ++j) {
        int col = j * 8 + tc * 2;
        uint32_t h0, l0u, h1, l1u;
        split_pair(fo[j][0] * i0, fo[j][1] * i0, h0, l0u);
        split_pair(fo[j][2] * i1, fo[j][3] * i1, h1, l1u);
        *(uint32_t*)(Ohi + r0 + col) = h0;
        *(uint32_t*)(Olo + r0 + col) = l0u;
        *(uint32_t*)(Ohi + r1 + col) = h1;
        *(uint32_t*)(Olo + r1 + col) = l1u;
    }
}

// ---------------- launch ------------------------------------------------------
extern "C" void kernel_launch(void* const* d_in, const int* in_sizes, int n_in,
                              void* d_out, int out_size)
{
    const float* key   = (const float*)d_in[0];
    const float* query = (const float*)d_in[1];
    const float* value = (const float*)d_in[2];
    const float* Wq    = (const float*)d_in[3];
    const float* Wk    = (const float*)d_in[4];
    const float* Wv    = (const float*)d_in[5];
    const float* Wo    = (const float*)d_in[6];
    const float* bo    = (const float*)d_in[7];
    float* out = (float*)d_out;

    __nv_bfloat16 *ahi, *alo, *whi, *wlo, *qhi, *qlo, *khi, *klo, *vhi, *vlo;
    cudaGetSymbolAddress((void**)&ahi, g_ahi);
    cudaGetSymbolAddress((void**)&alo, g_alo);
    cudaGetSymbolAddress((void**)&whi, g_whi);
    cudaGetSymbolAddress((void**)&wlo, g_wlo);
    cudaGetSymbolAddress((void**)&qhi, g_qhi);
    cudaGetSymbolAddress((void**)&qlo, g_qlo);
    cudaGetSymbolAddress((void**)&khi, g_khi);
    cudaGetSymbolAddress((void**)&klo, g_klo);
    cudaGetSymbolAddress((void**)&vhi, g_vhi);
    cudaGetSymbolAddress((void**)&vlo, g_vlo);

    cudaFuncSetAttribute(attn_mma,
                         cudaFuncAttributeMaxDynamicSharedMemorySize, ATTN_SMEM);
    cudaFuncSetAttribute(gemm_mma,
                         cudaFuncAttributeMaxDynamicSharedMemorySize, GEMM_SMEM);

    const int nact = M_ * D_;
    const int act_blocks = nact / 4 / 256;
    const int wt_blocks = (D_ * D_ + 255) / 256;
    dim3 gg(D_ / 128, M_ / 128);

    split_wt<<<wt_blocks, 256>>>(Wq, whi, wlo);
    split_act<<<act_blocks, 256>>>(query, ahi, alo, nact);
    gemm_mma<<<gg, 256, GEMM_SMEM>>>(ahi, alo, whi, wlo, nullptr, nullptr, qhi, qlo, 0.125f, 1);

    split_wt<<<wt_blocks, 256>>>(Wk, whi, wlo);
    split_act<<<act_blocks, 256>>>(key, ahi, alo, nact);
    gemm_mma<<<gg, 256, GEMM_SMEM>>>(ahi, alo, whi, wlo, nullptr, nullptr, khi, klo, 1.0f, 1);

    split_wt<<<wt_blocks, 256>>>(Wv, whi, wlo);
    split_act<<<act_blocks, 256>>>(value, ahi, alo, nact);
    gemm_mma<<<gg, 256, GEMM_SMEM>>>(ahi, alo, whi, wlo, nullptr, nullptr, vhi, vlo, 1.0f, 1);

    attn_mma<<<dim3(B_ * NH_, S_ / 128), 256, ATTN_SMEM>>>(
        qhi, qlo, khi, klo, vhi, vlo, ahi, alo);

    split_wt<<<wt_blocks, 256>>>(Wo, whi, wlo);
    gemm_mma<<<gg, 256, GEMM_SMEM>>>(ahi, alo, whi, wlo, bo, out, nullptr, nullptr, 1.0f, 0);
}

// round 5
// speedup vs baseline: 3.0935x; 1.1325x over previous
#include <cuda_runtime.h>
#include <cuda_bf16.h>
#include <cstdint>

#define B_  8
#define S_  2048
#define D_  512
#define NH_ 8
#define HD_ 64
#define M_  (B_*S_)

// ---------------- scratch (__device__ globals) ------------------------------
__device__ __nv_bfloat16 g_ahi[(size_t)M_ * D_];
__device__ __nv_bfloat16 g_alo[(size_t)M_ * D_];
__device__ __nv_bfloat16 g_whi[(size_t)D_ * D_];
__device__ __nv_bfloat16 g_wlo[(size_t)D_ * D_];
__device__ __nv_bfloat16 g_qhi[(size_t)M_ * D_];
__device__ __nv_bfloat16 g_qlo[(size_t)M_ * D_];
__device__ __nv_bfloat16 g_khi[(size_t)M_ * D_];
__device__ __nv_bfloat16 g_klo[(size_t)M_ * D_];
__device__ __nv_bfloat16 g_vhi[(size_t)M_ * D_];
__device__ __nv_bfloat16 g_vlo[(size_t)M_ * D_];

// ---------------- helpers ----------------------------------------------------
__device__ __forceinline__ uint32_t smem_u32(const void* p) {
    uint32_t a;
    asm("{ .reg .u64 t; cvta.to.shared.u64 t, %1; cvt.u32.u64 %0, t; }" : "=r"(a) : "l"(p));
    return a;
}
__device__ __forceinline__ void ldm4(uint32_t* r, uint32_t a) {
    asm volatile("ldmatrix.sync.aligned.m8n8.x4.shared.b16 {%0,%1,%2,%3}, [%4];"
        : "=r"(r[0]), "=r"(r[1]), "=r"(r[2]), "=r"(r[3]) : "r"(a));
}
__device__ __forceinline__ void ldm4t(uint32_t* r, uint32_t a) {
    asm volatile("ldmatrix.sync.aligned.m8n8.x4.trans.shared.b16 {%0,%1,%2,%3}, [%4];"
        : "=r"(r[0]), "=r"(r[1]), "=r"(r[2]), "=r"(r[3]) : "r"(a));
}
__device__ __forceinline__ void mma16816(float* d, const uint32_t* a, const uint32_t* b) {
    asm volatile("mma.sync.aligned.m16n8k16.row.col.f32.bf16.bf16.f32 "
        "{%0,%1,%2,%3}, {%4,%5,%6,%7}, {%8,%9}, {%0,%1,%2,%3};"
        : "+f"(d[0]), "+f"(d[1]), "+f"(d[2]), "+f"(d[3])
        : "r"(a[0]), "r"(a[1]), "r"(a[2]), "r"(a[3]), "r"(b[0]), "r"(b[1]));
}
__device__ __forceinline__ uint32_t pack_bf(float a, float b) {
    __nv_bfloat162 t = __floats2bfloat162_rn(a, b);
    return *reinterpret_cast<uint32_t*>(&t);
}
__device__ __forceinline__ void split_pair(float a, float b, uint32_t& hi, uint32_t& lo) {
    __nv_bfloat16 ha = __float2bfloat16(a), hb = __float2bfloat16(b);
    __nv_bfloat162 hv(ha, hb);
    hi = *reinterpret_cast<uint32_t*>(&hv);
    lo = pack_bf(a - __bfloat162float(ha), b - __bfloat162float(hb));
}
#define CPA16(dst, src) asm volatile("cp.async.cg.shared.global [%0], [%1], 16;" :: "r"(dst), "l"(src))
#define CP_COMMIT()     asm volatile("cp.async.commit_group;" ::: "memory")
#define CP_WAIT1()      asm volatile("cp.async.wait_group 1;" ::: "memory")
#define CP_WAIT0()      asm volatile("cp.async.wait_group 0;" ::: "memory")

// ---------------- prep: fp32 -> bf16 hi/lo -----------------------------------
__global__ __launch_bounds__(256) void split_act(
    const float* __restrict__ x, __nv_bfloat16* __restrict__ hi,
    __nv_bfloat16* __restrict__ lo, int n)
{
    int i = (blockIdx.x * 256 + threadIdx.x) * 4;
    if (i >= n) return;
    float4 v = *(const float4*)(x + i);
    uint32_t h0, l0, h1, l1;
    split_pair(v.x, v.y, h0, l0);
    split_pair(v.z, v.w, h1, l1);
    *(uint32_t*)(hi + i)     = h0;
    *(uint32_t*)(hi + i + 2) = h1;
    *(uint32_t*)(lo + i)     = l0;
    *(uint32_t*)(lo + i + 2) = l1;
}

__global__ __launch_bounds__(256) void split_wt(
    const float* __restrict__ W, __nv_bfloat16* __restrict__ hi,
    __nv_bfloat16* __restrict__ lo)
{
    int t = blockIdx.x * 256 + threadIdx.x;
    if (t >= D_ * D_) return;
    int k = t & (D_ - 1);
    int n = t >> 9;
    float v = W[(size_t)k * D_ + n];
    __nv_bfloat16 h = __float2bfloat16(v);
    hi[t] = h;
    lo[t] = __float2bfloat16(v - __bfloat162float(h));
}

// ---------------- GEMM (double-buffered cp.async) ----------------------------
#define GS 40
#define GEMM_ARR (128 * GS * 2)
#define GEMM_STAGE (4 * GEMM_ARR)
#define GEMM_SMEM (2 * GEMM_STAGE)

__global__ __launch_bounds__(256) void gemm_mma(
    const __nv_bfloat16* __restrict__ Ahi, const __nv_bfloat16* __restrict__ Alo,
    const __nv_bfloat16* __restrict__ Whi, const __nv_bfloat16* __restrict__ Wlo,
    const float* __restrict__ bias, float* __restrict__ Yf,
    __nv_bfloat16* __restrict__ Yhi, __nv_bfloat16* __restrict__ Ylo,
    float scale, int mode)
{
    extern __shared__ __align__(16) char smg[];
    const uint32_t sb = smem_u32(smg);

    const int tid  = threadIdx.x;
    const int lane = tid & 31;
    const int wid  = tid >> 5;
    const int wm   = wid >> 2;
    const int wn   = wid & 3;
    const int m0   = blockIdx.y * 128;
    const int n0   = blockIdx.x * 128;
    const int g    = lane >> 2;
    const int tc   = lane & 3;

    float acc[4][4][4];
#pragma unroll
    for (int i = 0; i < 4; ++i)
#pragma unroll
        for (int j = 0; j < 4; ++j)
#pragma unroll
            for (int e = 0; e < 4; ++e) acc[i][j][e] = 0.f;

    const int prow = tid >> 2;
    const int pqb  = (tid & 3) << 4;
    auto prefetch = [&](int c, int st) {
        const uint32_t base = sb + st * GEMM_STAGE;
#pragma unroll
        for (int i = 0; i < 2; ++i) {
            int row = prow + i * 64;
            uint32_t so = row * (GS * 2) + pqb;
            size_t ga = (size_t)(m0 + row) * D_ + c * 32 + (pqb >> 1);
            size_t gb = (size_t)(n0 + row) * D_ + c * 32 + (pqb >> 1);
            CPA16(base + so,                ((const char*)(Ahi + ga)));
            CPA16(base + GEMM_ARR + so,     ((const char*)(Alo + ga)));
            CPA16(base + 2 * GEMM_ARR + so, ((const char*)(Whi + gb)));
            CPA16(base + 3 * GEMM_ARR + so, ((const char*)(Wlo + gb)));
        }
    };

    prefetch(0, 0);
    CP_COMMIT();

    const uint32_t aofs = ((wm * 64 + (lane & 15)) * GS + (lane >> 4) * 8) * 2;
    const int bn = wn * 32 + (lane & 7) + (lane >> 4) * 8;
    const int bko = ((lane >> 3) & 1) * 8;

    for (int c = 0; c < 16; ++c) {
        const int st = c & 1;
        if (c + 1 < 16) { prefetch(c + 1, st ^ 1); CP_COMMIT(); CP_WAIT1(); }
        else CP_WAIT0();
        __syncthreads();

        const uint32_t sAh = sb + st * GEMM_STAGE;
        const uint32_t sAl = sAh + GEMM_ARR;
        const uint32_t sBh = sAh + 2 * GEMM_ARR;
        const uint32_t sBl = sAh + 3 * GEMM_ARR;

#pragma unroll
        for (int s = 0; s < 2; ++s) {
            uint32_t ah[4][4], al[4][4], bh[4][2], bl[4][2];
#pragma unroll
            for (int mf = 0; mf < 4; ++mf) {
                ldm4(ah[mf], sAh + aofs + s * 32 + mf * 16 * GS * 2);
                ldm4(al[mf], sAl + aofs + s * 32 + mf * 16 * GS * 2);
            }
            const int bk = s * 16 + bko;
#pragma unroll
            for (int jp = 0; jp < 2; ++jp) {
                uint32_t r[4];
                ldm4(r, sBh + ((bn + jp * 16) * GS + bk) * 2);
                bh[jp * 2][0] = r[0]; bh[jp * 2][1] = r[1];
                bh[jp * 2 + 1][0] = r[2]; bh[jp * 2 + 1][1] = r[3];
                ldm4(r, sBl + ((bn + jp * 16) * GS + bk) * 2);
                bl[jp * 2][0] = r[0]; bl[jp * 2][1] = r[1];
                bl[jp * 2 + 1][0] = r[2]; bl[jp * 2 + 1][1] = r[3];
            }
#pragma unroll
            for (int mf = 0; mf < 4; ++mf)
#pragma unroll
                for (int nf = 0; nf < 4; ++nf) {
                    mma16816(acc[mf][nf], ah[mf], bh[nf]);
                    mma16816(acc[mf][nf], ah[mf], bl[nf]);
                    mma16816(acc[mf][nf], al[mf], bh[nf]);
                }
        }
        __syncthreads();
    }

#pragma unroll
    for (int mf = 0; mf < 4; ++mf)
#pragma unroll
        for (int nf = 0; nf < 4; ++nf) {
            int row = m0 + wm * 64 + mf * 16 + g;
            int col = n0 + wn * 32 + nf * 8 + tc * 2;
            float d0 = acc[mf][nf][0], d1 = acc[mf][nf][1];
            float d2 = acc[mf][nf][2], d3 = acc[mf][nf][3];
            if (mode == 0) {
                float b0 = bias[col], b1 = bias[col + 1];
                *(float2*)(Yf + (size_t)row * D_ + col)       = make_float2(d0 + b0, d1 + b1);
                *(float2*)(Yf + (size_t)(row + 8) * D_ + col) = make_float2(d2 + b0, d3 + b1);
            } else {
                uint32_t h0, l0, h1, l1;
                split_pair(d0 * scale, d1 * scale, h0, l0);
                split_pair(d2 * scale, d3 * scale, h1, l1);
                *(uint32_t*)(Yhi + (size_t)row * D_ + col)       = h0;
                *(uint32_t*)(Ylo + (size_t)row * D_ + col)       = l0;
                *(uint32_t*)(Yhi + (size_t)(row + 8) * D_ + col) = h1;
                *(uint32_t*)(Ylo + (size_t)(row + 8) * D_ + col) = l1;
            }
        }
}

// ---------------- attention: 4 warps x 32 query rows, 128-q tile -------------
#define AS 72
#define KV_ARR (64 * AS * 2)
#define KV_STAGE (4 * KV_ARR)
#define Q_BYTES (2 * 128 * AS * 2)
#define ATTN_SMEM (Q_BYTES + 2 * KV_STAGE)

__global__ __launch_bounds__(128, 2) void attn_mma(
    const __nv_bfloat16* __restrict__ Qh, const __nv_bfloat16* __restrict__ Ql,
    const __nv_bfloat16* __restrict__ Kh, const __nv_bfloat16* __restrict__ Kl,
    const __nv_bfloat16* __restrict__ Vh, const __nv_bfloat16* __restrict__ Vl,
    __nv_bfloat16* __restrict__ Ohi, __nv_bfloat16* __restrict__ Olo)
{
    extern __shared__ __align__(16) char sma[];
    __nv_bfloat16* smb = (__nv_bfloat16*)sma;
    const uint32_t sb = smem_u32(sma);

    const int tid  = threadIdx.x;
    const int lane = tid & 31;
    const int wid  = tid >> 5;          // 0..3, warp owns rows wid*32 .. +31
    const int bh   = blockIdx.x;
    const int b    = bh >> 3;
    const int h    = bh & 7;
    const int q0   = blockIdx.y * 128;
    const int g    = lane >> 2;
    const int tc   = lane & 3;

    // ---- Q tile (128 x 64, hi+lo) ----
#pragma unroll
    for (int i = 0; i < 8; ++i) {
        int idx = tid + i * 128;
        int row = idx >> 3, q = (idx & 7) << 3;
        size_t gofs = ((size_t)(b * S_ + q0 + row)) * D_ + h * HD_ + q;
        *(uint4*)&smb[row * AS + q]            = *(const uint4*)(Qh + gofs);
        *(uint4*)&smb[128 * AS + row * AS + q] = *(const uint4*)(Ql + gofs);
    }

    // KV prefetch: 4 chunks per array per thread (128 threads)
    const int prow = tid >> 3;
    const int pqb  = (tid & 7) << 4;
    auto prefetch = [&](int kt, int st) {
        const uint32_t base = sb + Q_BYTES + st * KV_STAGE;
        size_t grow = (size_t)(b * S_ + kt * 64) * D_ + h * HD_;
#pragma unroll
        for (int i = 0; i < 4; ++i) {
            int row = prow + i * 16;
            uint32_t so = row * (AS * 2) + pqb;
            size_t go = grow + (size_t)row * D_ + (pqb >> 1);
            CPA16(base + so,              ((const char*)(Kh + go)));
            CPA16(base + KV_ARR + so,     ((const char*)(Kl + go)));
            CPA16(base + 2 * KV_ARR + so, ((const char*)(Vh + go)));
            CPA16(base + 3 * KV_ARR + so, ((const char*)(Vl + go)));
        }
    };
    prefetch(0, 0);
    CP_COMMIT();
    __syncthreads();

    const float NEG_INF = __int_as_float(0xff800000u);
    float fo[2][8][4];
#pragma unroll
    for (int qf = 0; qf < 2; ++qf)
#pragma unroll
        for (int j = 0; j < 8; ++j)
#pragma unroll
            for (int e = 0; e < 4; ++e) fo[qf][j][e] = 0.f;
    float mr[2][2] = {{NEG_INF, NEG_INF}, {NEG_INF, NEG_INF}};
    float lr[2][2] = {{0.f, 0.f}, {0.f, 0.f}};

    const int bn  = (lane & 7) + (lane >> 4) * 8;
    const int bko = ((lane >> 3) & 1) * 8;
    const int vk0 = (lane & 7) + ((lane >> 3) & 1) * 8;
    const int vd  = (lane >> 4) * 8;
    // Q frag base offsets (per qf): row = wid*32 + qf*16 + (lane&15)
    const uint32_t qfo0 = ((wid * 32 + (lane & 15)) * AS + (lane >> 4) * 8) * 2;
    const uint32_t qfo1 = qfo0 + 16 * AS * 2;

    for (int kt = 0; kt < S_ / 64; ++kt) {
        const int st = kt & 1;
        if (kt + 1 < S_ / 64) { prefetch(kt + 1, st ^ 1); CP_COMMIT(); CP_WAIT1(); }
        else CP_WAIT0();
        __syncthreads();

        const uint32_t oKh = sb + Q_BYTES + st * KV_STAGE;
        const uint32_t oKl = oKh + KV_ARR;
        const uint32_t oVh = oKh + 2 * KV_ARR;
        const uint32_t oVl = oKh + 3 * KV_ARR;

        // ---- S = Q K^T (both q-frags share K frags) ----
        float fs[2][8][4];
#pragma unroll
        for (int qf = 0; qf < 2; ++qf)
#pragma unroll
            for (int j = 0; j < 8; ++j)
#pragma unroll
                for (int e = 0; e < 4; ++e) fs[qf][j][e] = 0.f;

#pragma unroll
        for (int s = 0; s < 4; ++s) {
            uint32_t bkh[8][2], bkl[8][2];
            const int bk = s * 16 + bko;
#pragma unroll
            for (int jp = 0; jp < 4; ++jp) {
                uint32_t r[4];
                ldm4(r, oKh + ((bn + jp * 16) * AS + bk) * 2);
                bkh[jp * 2][0] = r[0]; bkh[jp * 2][1] = r[1];
                bkh[jp * 2 + 1][0] = r[2]; bkh[jp * 2 + 1][1] = r[3];
                ldm4(r, oKl + ((bn + jp * 16) * AS + bk) * 2);
                bkl[jp * 2][0] = r[0]; bkl[jp * 2][1] = r[1];
                bkl[jp * 2 + 1][0] = r[2]; bkl[jp * 2 + 1][1] = r[3];
            }
#pragma unroll
            for (int qf = 0; qf < 2; ++qf) {
                uint32_t qh[4], ql[4];
                const uint32_t qo = (qf ? qfo1 : qfo0) + s * 32;
                ldm4(qh, sb + qo);
                ldm4(ql, sb + (uint32_t)(128 * AS * 2) + qo);
#pragma unroll
                for (int j = 0; j < 8; ++j) {
                    mma16816(fs[qf][j], qh, bkh[j]);
                    mma16816(fs[qf][j], qh, bkl[j]);
                    mma16816(fs[qf][j], ql, bkh[j]);
                }
            }
        }

        // ---- online softmax + P conversion, per q-frag ----
        uint32_t ph[2][4][4], pl[2][4][4];
#pragma unroll
        for (int qf = 0; qf < 2; ++qf) {
            float mx0 = NEG_INF, mx1 = NEG_INF;
#pragma unroll
            for (int j = 0; j < 8; ++j) {
                mx0 = fmaxf(mx0, fmaxf(fs[qf][j][0], fs[qf][j][1]));
                mx1 = fmaxf(mx1, fmaxf(fs[qf][j][2], fs[qf][j][3]));
            }
            mx0 = fmaxf(mx0, __shfl_xor_sync(0xffffffffu, mx0, 1));
            mx0 = fmaxf(mx0, __shfl_xor_sync(0xffffffffu, mx0, 2));
            mx1 = fmaxf(mx1, __shfl_xor_sync(0xffffffffu, mx1, 1));
            mx1 = fmaxf(mx1, __shfl_xor_sync(0xffffffffu, mx1, 2));
            float mn0 = fmaxf(mr[qf][0], mx0), mn1 = fmaxf(mr[qf][1], mx1);
            float c0 = __expf(mr[qf][0] - mn0), c1 = __expf(mr[qf][1] - mn1);
            mr[qf][0] = mn0; mr[qf][1] = mn1;

            float s0 = 0.f, s1 = 0.f;
#pragma unroll
            for (int j = 0; j < 8; ++j) {
                fs[qf][j][0] = __expf(fs[qf][j][0] - mn0);
                fs[qf][j][1] = __expf(fs[qf][j][1] - mn0);
                fs[qf][j][2] = __expf(fs[qf][j][2] - mn1);
                fs[qf][j][3] = __expf(fs[qf][j][3] - mn1);
                s0 += fs[qf][j][0] + fs[qf][j][1];
                s1 += fs[qf][j][2] + fs[qf][j][3];
            }
            s0 += __shfl_xor_sync(0xffffffffu, s0, 1);
            s0 += __shfl_xor_sync(0xffffffffu, s0, 2);
            s1 += __shfl_xor_sync(0xffffffffu, s1, 1);
            s1 += __shfl_xor_sync(0xffffffffu, s1, 2);
            lr[qf][0] = lr[qf][0] * c0 + s0;
            lr[qf][1] = lr[qf][1] * c1 + s1;
#pragma unroll
            for (int j = 0; j < 8; ++j) {
                fo[qf][j][0] *= c0; fo[qf][j][1] *= c0;
                fo[qf][j][2] *= c1; fo[qf][j][3] *= c1;
            }
#pragma unroll
            for (int kk = 0; kk < 4; ++kk) {
                split_pair(fs[qf][2 * kk][0],     fs[qf][2 * kk][1],     ph[qf][kk][0], pl[qf][kk][0]);
                split_pair(fs[qf][2 * kk][2],     fs[qf][2 * kk][3],     ph[qf][kk][1], pl[qf][kk][1]);
                split_pair(fs[qf][2 * kk + 1][0], fs[qf][2 * kk + 1][1], ph[qf][kk][2], pl[qf][kk][2]);
                split_pair(fs[qf][2 * kk + 1][2], fs[qf][2 * kk + 1][3], ph[qf][kk][3], pl[qf][kk][3]);
            }
        }

        // ---- O += P V (both q-frags share V frags) ----
#pragma unroll
        for (int kk = 0; kk < 4; ++kk) {
            uint32_t bvh[8][2], bvl[8][2];
            const int vk = kk * 16 + vk0;
#pragma unroll
            for (int jp = 0; jp < 4; ++jp) {
                uint32_t r[4];
                ldm4t(r, oVh + (vk * AS + vd + jp * 16) * 2);
                bvh[jp * 2][0] = r[0]; bvh[jp * 2][1] = r[1];
                bvh[jp * 2 + 1][0] = r[2]; bvh[jp * 2 + 1][1] = r[3];
                ldm4t(r, oVl + (vk * AS + vd + jp * 16) * 2);
                bvl[jp * 2][0] = r[0]; bvl[jp * 2][1] = r[1];
                bvl[jp * 2 + 1][0] = r[2]; bvl[jp * 2 + 1][1] = r[3];
            }
#pragma unroll
            for (int qf = 0; qf < 2; ++qf)
#pragma unroll
                for (int j = 0; j < 8; ++j) {
                    mma16816(fo[qf][j], ph[qf][kk], bvh[j]);
                    mma16816(fo[qf][j], ph[qf][kk], bvl[j]);
                    mma16816(fo[qf][j], pl[qf][kk], bvh[j]);
                }
        }
        __syncthreads();
    }

    // ---- epilogue ----
#pragma unroll
    for (int qf = 0; qf < 2; ++qf) {
        float i0 = 1.f / lr[qf][0], i1 = 1.f / lr[qf][1];
        const size_t r0 = (size_t)(b * S_ + q0 + wid * 32 + qf * 16 + g) * D_ + h * HD_;
        const size_t r1 = r0 + 8 * D_;
#pragma unroll
        for (int j = 0; j < 8; ++j) {
            int col = j * 8 + tc * 2;
            uint32_t h0, l0u, h1, l1u;
            split_pair(fo[qf][j][0] * i0, fo[qf][j][1] * i0, h0, l0u);
            split_pair(fo[qf][j][2] * i1, fo[qf][j][3] * i1, h1, l1u);
            *(uint32_t*)(Ohi + r0 + col) = h0;
            *(uint32_t*)(Olo + r0 + col) = l0u;
            *(uint32_t*)(Ohi + r1 + col) = h1;
            *(uint32_t*)(Olo + r1 + col) = l1u;
        }
    }
}

// ---------------- launch ------------------------------------------------------
extern "C" void kernel_launch(void* const* d_in, const int* in_sizes, int n_in,
                              void* d_out, int out_size)
{
    const float* key   = (const float*)d_in[0];
    const float* query = (const float*)d_in[1];
    const float* value = (const float*)d_in[2];
    const float* Wq    = (const float*)d_in[3];
    const float* Wk    = (const float*)d_in[4];
    const float* Wv    = (const float*)d_in[5];
    const float* Wo    = (const float*)d_in[6];
    const float* bo    = (const float*)d_in[7];
    float* out = (float*)d_out;

    __nv_bfloat16 *ahi, *alo, *whi, *wlo, *qhi, *qlo, *khi, *klo, *vhi, *vlo;
    cudaGetSymbolAddress((void**)&ahi, g_ahi);
    cudaGetSymbolAddress((void**)&alo, g_alo);
    cudaGetSymbolAddress((void**)&whi, g_whi);
    cudaGetSymbolAddress((void**)&wlo, g_wlo);
    cudaGetSymbolAddress((void**)&qhi, g_qhi);
    cudaGetSymbolAddress((void**)&qlo, g_qlo);
    cudaGetSymbolAddress((void**)&khi, g_khi);
    cudaGetSymbolAddress((void**)&klo, g_klo);
    cudaGetSymbolAddress((void**)&vhi, g_vhi);
    cudaGetSymbolAddress((void**)&vlo, g_vlo);

    cudaFuncSetAttribute(attn_mma,
                         cudaFuncAttributeMaxDynamicSharedMemorySize, ATTN_SMEM);
    cudaFuncSetAttribute(gemm_mma,
                         cudaFuncAttributeMaxDynamicSharedMemorySize, GEMM_SMEM);

    const int nact = M_ * D_;
    const int act_blocks = nact / 4 / 256;
    const int wt_blocks = (D_ * D_ + 255) / 256;
    dim3 gg(D_ / 128, M_ / 128);

    split_wt<<<wt_blocks, 256>>>(Wq, whi, wlo);
    split_act<<<act_blocks, 256>>>(query, ahi, alo, nact);
    gemm_mma<<<gg, 256, GEMM_SMEM>>>(ahi, alo, whi, wlo, nullptr, nullptr, qhi, qlo, 0.125f, 1);

    split_wt<<<wt_blocks, 256>>>(Wk, whi, wlo);
    split_act<<<act_blocks, 256>>>(key, ahi, alo, nact);
    gemm_mma<<<gg, 256, GEMM_SMEM>>>(ahi, alo, whi, wlo, nullptr, nullptr, khi, klo, 1.0f, 1);

    split_wt<<<wt_blocks, 256>>>(Wv, whi, wlo);
    split_act<<<act_blocks, 256>>>(value, ahi, alo, nact);
    gemm_mma<<<gg, 256, GEMM_SMEM>>>(ahi, alo, whi, wlo, nullptr, nullptr, vhi, vlo, 1.0f, 1);

    attn_mma<<<dim3(B_ * NH_, S_ / 128), 128, ATTN_SMEM>>>(
        qhi, qlo, khi, klo, vhi, vlo, ahi, alo);

    split_wt<<<wt_blocks, 256>>>(Wo, whi, wlo);
    gemm_mma<<<gg, 256, GEMM_SMEM>>>(ahi, alo, whi, wlo, bo, out, nullptr, nullptr, 1.0f, 0);
}